// round 5
// baseline (speedup 1.0000x reference)
#include <cuda_runtime.h>
#include <math.h>
#include <stdint.h>

#define D_MODEL   2048
#define Q_LATD    1536
#define KV_LATD   512
#define NUM_HEADS 16
#define HEAD_DIM  128
#define BATCH     2
#define SEQ       2048
#define ROWS      (BATCH * SEQ)      // 4096
#define QK_DIM    256                // head_dim(128) + rope(128)

// ---------------- scratch (device globals; no allocation allowed) ----------
__device__ float g_qlat[ROWS * Q_LATD];
__device__ float g_kvlat[ROWS * KV_LATD];
__device__ float g_qnew[(size_t)ROWS * NUM_HEADS * QK_DIM];   // [b,s,h,256]
__device__ float g_knew[(size_t)ROWS * NUM_HEADS * QK_DIM];   // [b,s,h,256] (d-packed)
__device__ float g_v[(size_t)ROWS * D_MODEL];                 // [b,s,h*128] (col-packed)
__device__ float g_attn[(size_t)ROWS * D_MODEL];
__device__ float g_qrt[(size_t)ROWS * D_MODEL];
__device__ float g_krt[(size_t)ROWS * HEAD_DIM];
// pre-rounded inputs + transposed/packed weights
__device__ float g_rinq[(size_t)ROWS * D_MODEL];
__device__ float g_rink[(size_t)ROWS * D_MODEL];
__device__ float g_tWqd[(size_t)Q_LATD * D_MODEL];
__device__ float g_tWkvd[(size_t)KV_LATD * D_MODEL];
__device__ float g_tWqu[(size_t)D_MODEL * Q_LATD];
__device__ float g_tWqr[(size_t)D_MODEL * Q_LATD];
__device__ float g_tWku[(size_t)D_MODEL * KV_LATD];
__device__ float g_tWvu[(size_t)D_MODEL * KV_LATD];
__device__ float g_tWkr[(size_t)HEAD_DIM * D_MODEL];
__device__ float g_tWo[(size_t)D_MODEL * D_MODEL];

// ---------------- helpers --------------------------------------------------
__device__ __forceinline__ uint32_t f2tf(float x) {
    uint32_t u;
    asm("cvt.rna.tf32.f32 %0, %1;" : "=r"(u) : "f"(x));
    return u;
}

__device__ __forceinline__ uint32_t sptr(const void* p) {
    return (uint32_t)__cvta_generic_to_shared(p);
}

__device__ __forceinline__ void mma8(float c[4],
    uint32_t a0, uint32_t a1, uint32_t a2, uint32_t a3,
    uint32_t b0, uint32_t b1)
{
    asm volatile(
        "mma.sync.aligned.m16n8k8.row.col.f32.tf32.tf32.f32 "
        "{%0,%1,%2,%3}, {%4,%5,%6,%7}, {%8,%9}, {%0,%1,%2,%3};\n"
        : "+f"(c[0]), "+f"(c[1]), "+f"(c[2]), "+f"(c[3])
        : "r"(a0), "r"(a1), "r"(a2), "r"(a3), "r"(b0), "r"(b1));
}

__device__ __forceinline__ void ldmx4(uint32_t a[4], uint32_t addr) {
    asm volatile(
        "ldmatrix.sync.aligned.m8n8.x4.shared.b16 {%0,%1,%2,%3}, [%4];"
        : "=r"(a[0]), "=r"(a[1]), "=r"(a[2]), "=r"(a[3]) : "r"(addr));
}

#define CP16(dst, src) \
    asm volatile("cp.async.cg.shared.global [%0], [%1], 16;" :: "r"(dst), "l"(src))
#define CP_COMMIT() asm volatile("cp.async.commit_group;" ::: "memory")
#define CP_WAIT1()  asm volatile("cp.async.wait_group 1;" ::: "memory")
#define CP_WAIT2()  asm volatile("cp.async.wait_group 2;" ::: "memory")

// exp(x) for x <= 0 on the FMA pipe only (no MUFU)
__device__ __forceinline__ float fast_exp(float x) {
    float y  = fmaxf(x * 1.4426950408889634f, -126.0f);
    float tb = y + 12582912.0f;
    float nf = tb - 12582912.0f;
    float u  = (y - nf) * 0.6931471805599453f;
    float p  = fmaf(u, 0.008333334f, 0.041666668f);
    p = fmaf(p, u, 0.16666667f);
    p = fmaf(p, u, 0.5f);
    p = fmaf(p, u, 1.0f);
    p = fmaf(p, u, 1.0f);
    return p * __int_as_float(((int)nf + 127) << 23);
}

// digit-swap within a 16-chunk: stored pos 4t+j holds original t+4j (self-framed)
__device__ __forceinline__ int permk(int k) {
    return (k & ~15) | (((k & 3) << 2) | ((k >> 2) & 3));
}

// ---------------- pre-pass kernels -----------------------------------------
__global__ void roundcopy(const float* __restrict__ in, float* __restrict__ out, int n)
{
    int i = (blockIdx.x * 256 + threadIdx.x) * 4;
    if (i >= n) return;
    float4 v = *(const float4*)(in + i);
    *(uint4*)(out + i) = make_uint4(f2tf(v.x), f2tf(v.y), f2tf(v.z), f2tf(v.w));
}

// W[K][N] -> Wt[N][K-packed] with tf32 rounding
__global__ void wtrans(const float* __restrict__ W, float* __restrict__ Wt, int K, int N)
{
    __shared__ float tile[32][33];
    const int k0 = blockIdx.y * 32, n0 = blockIdx.x * 32;
    const int tx = threadIdx.x, ty = threadIdx.y;   // 32 x 8
#pragma unroll
    for (int r = ty; r < 32; r += 8)
        tile[r][tx] = W[(size_t)(k0 + r) * N + n0 + tx];
    __syncthreads();
#pragma unroll
    for (int r = ty; r < 32; r += 8) {
        const int n = n0 + r, k = k0 + tx;
        Wt[(size_t)n * K + permk(k)] = __uint_as_float(f2tf(tile[tx][r]));
    }
}

// ---------------- tf32 GEMM: C[M,N] = A[M,K] @ Bt^T ------------------------
// A natural [M][K] (pre-rounded), Bt transposed+packed [N][K] (pre-rounded).
// block 128x128, BK=16, 4-stage cp.async, A ldmatrix, B LDS.128.
// mode: 0 identity; 1 head-interleave; 2 interleave+kpack; 3 vpack.
__global__ void __launch_bounds__(256, 2) tf32gemm(
    const float* __restrict__ A, const float* __restrict__ Bt,
    float* __restrict__ C, const float* __restrict__ bias,
    int M, int N, int K, int ldc, int mode, int rnd)
{
    extern __shared__ uint32_t sm[];   // A: 4 x 128x20  then B: 4 x 128x20
    const int tid  = threadIdx.x;
    const int lane = tid & 31, w = tid >> 5;
    const int g = lane >> 2, t = lane & 3;
    const int wm = (w & 1) * 64, wn = (w >> 1) * 32;
    const int bm = blockIdx.y * 128, bn = blockIdx.x * 128;

    const int sr = tid >> 1, sk = (tid & 1) * 8;   // staging row / k-half
    const uint32_t sA0 = sptr(sm) + ((sr * 20 + sk) << 2);
    const uint32_t sB0 = sA0 + 40960;
    const float* Agb = A  + (size_t)(bm + sr) * K + sk;
    const float* Bgb = Bt + (size_t)(bn + sr) * K + sk;

    const uint32_t aFrag = sptr(sm) +
        (((wm + (lane & 15)) * 20 + ((lane >> 4) << 2)) << 2);

    float acc[4][4][4];
#pragma unroll
    for (int i = 0; i < 4; i++)
#pragma unroll
        for (int j = 0; j < 4; j++)
#pragma unroll
            for (int e = 0; e < 4; e++) acc[i][j][e] = 0.f;

    const int nk = K >> 4;

    auto issueStage = [&](int s) {
        const int slot = s & 3;
        const float* Ap = Agb + s * 16;
        const uint32_t ad = sA0 + slot * 10240;
        CP16(ad, Ap); CP16(ad + 16, Ap + 4);
        const float* Bp = Bgb + s * 16;
        const uint32_t bd = sB0 + slot * 10240;
        CP16(bd, Bp); CP16(bd + 16, Bp + 4);
    };

    issueStage(0); CP_COMMIT();
    issueStage(1); CP_COMMIT();
    issueStage(2); CP_COMMIT();

    for (int kt = 0; kt < nk; kt++) {
        CP_WAIT2();
        __syncthreads();
        if (kt + 3 < nk) issueStage(kt + 3);
        CP_COMMIT();

        const int slot = kt & 3;
        const uint32_t aS = aFrag + slot * 10240;
        const uint32_t* Bsl = sm + 10240 + slot * 2560;

        uint4 bq[4];
#pragma unroll
        for (int nt = 0; nt < 4; nt++)
            bq[nt] = *(const uint4*)&Bsl[(wn + nt * 8 + g) * 20 + t * 4];

#pragma unroll
        for (int ks = 0; ks < 2; ks++) {
            uint32_t af[4][4];
#pragma unroll
            for (int mt = 0; mt < 4; mt++)
                ldmx4(af[mt], aS + mt * 1280 + ks * 32);
#pragma unroll
            for (int mt = 0; mt < 4; mt++)
#pragma unroll
                for (int nt = 0; nt < 4; nt++)
                    mma8(acc[mt][nt], af[mt][0], af[mt][1], af[mt][2], af[mt][3],
                         ks ? bq[nt].z : bq[nt].x, ks ? bq[nt].w : bq[nt].y);
        }
    }

#pragma unroll
    for (int mt = 0; mt < 4; mt++) {
#pragma unroll
        for (int nt = 0; nt < 4; nt++) {
            const int r = bm + wm + mt * 16 + g;
            const int c = bn + wn + nt * 8 + 2 * t;
#pragma unroll
            for (int e = 0; e < 4; e++) {
                const int rr = r + ((e >> 1) << 3);
                const int cc = c + (e & 1);
                float v = acc[mt][nt][e];
                if (bias) v += bias[cc];
                if (rnd) v = __uint_as_float(f2tf(v));
                int oc;
                if (mode == 0)      oc = cc;
                else if (mode == 1) oc = ((cc >> 7) << 8) + (cc & 127);
                else if (mode == 2) {
                    int hb = (cc >> 7) << 8, ww = cc & 127;
                    oc = hb + permk(ww);
                } else {
                    int hb = cc & ~127, ww = cc & 127;
                    oc = hb + ((ww & 7) << 4) + ((ww >> 3) & 15);
                }
                C[(size_t)rr * ldc + oc] = v;
            }
        }
    }
}

// ---------------- rope on q (full 2048 dims) -> q_new[...,128:256] ---------
__global__ void rope_q_kernel(const float* __restrict__ in, float* __restrict__ qnew)
{
    int j = blockIdx.x * blockDim.x + threadIdx.x;
    int row = blockIdx.y;
    if (j >= 1024) return;
    int pos = row & (SEQ - 1);
    float inv = powf(10000.0f, -(float)j * (1.0f / 1024.0f));
    float ang = (float)pos * inv;
    float sn, cs;
    sincosf(ang, &sn, &cs);
    float x1 = in[(size_t)row * 2048 + j];
    float x2 = in[(size_t)row * 2048 + j + 1024];
    float o1 = __uint_as_float(f2tf(x1 * cs - x2 * sn));
    float o2 = __uint_as_float(f2tf(x2 * cs + x1 * sn));
    int c1 = j, c2 = j + 1024;
    qnew[(size_t)row * 4096 + (c1 >> 7) * 256 + (c1 & 127) + 128] = o1;
    qnew[(size_t)row * 4096 + (c2 >> 7) * 256 + (c2 & 127) + 128] = o2;
}

// ---------------- rope on k + broadcast to all heads (k-packed) ------------
__global__ void rope_k_kernel(const float* __restrict__ in, float* __restrict__ knew)
{
    int j = threadIdx.x;          // 0..63
    int row = blockIdx.x;
    int pos = row & (SEQ - 1);
    float inv = powf(10000.0f, -(float)j * (1.0f / 64.0f));
    float ang = (float)pos * inv;
    float sn, cs;
    sincosf(ang, &sn, &cs);
    float x1 = in[(size_t)row * 128 + j];
    float x2 = in[(size_t)row * 128 + j + 64];
    float o1 = __uint_as_float(f2tf(x1 * cs - x2 * sn));
    float o2 = __uint_as_float(f2tf(x2 * cs + x1 * sn));
    const int p1 = permk(128 + j);        // packed pos within head 256-block
    const int p2 = permk(128 + j + 64);
    float* base = knew + (size_t)row * 4096;
#pragma unroll
    for (int h = 0; h < NUM_HEADS; h++) {
        base[h * 256 + p1] = o1;
        base[h * 256 + p2] = o2;
    }
}

// ---------------- flash attention v4 ---------------------------------------
// Bq=128 (8 warps x 16 rows), Bk=16, 3-buffer cp.async K/V, packed K/V frags.
#define BQ  128
#define BK  16
#define SQS 260
#define SKS 268
#define SVS 132
#define SPS 36
#define Q_WORDS  (BQ * SQS)              // 33280
#define K_WORDS  (3 * BK * SKS)          // 12864
#define V_WORDS  (3 * BK * SVS)          // 6336
#define P_WORDS  (BQ * SPS)              // 4608
#define ATT_SMEM_BYTES ((Q_WORDS + K_WORDS + V_WORDS + P_WORDS) * 4)  // 228352

__global__ void __launch_bounds__(256, 1) mla_attn_tf32(
    const float* __restrict__ Qn, const float* __restrict__ Kn,
    const float* __restrict__ Vp, float* __restrict__ Op)
{
    extern __shared__ uint32_t sw[];
    uint32_t* sQ = sw;
    uint32_t* sK = sQ + Q_WORDS;
    uint32_t* sV = sK + K_WORDS;
    uint32_t* sP = sV + V_WORDS;

    const int tid = threadIdx.x, lane = tid & 31, w = tid >> 5;
    const int g = lane >> 2, t = lane & 3;
    const int qt = blockIdx.x, h = blockIdx.y, b = blockIdx.z;
    const int q0 = w * 16;

    const uint32_t qAddr = sptr(sQ) +
        (((q0 + (lane & 15)) * SQS + ((lane >> 4) << 2)) << 2);
    const uint32_t pAddr = sptr(sP) +
        (((q0 + (lane & 15)) * SPS + ((lane >> 4) << 2)) << 2);
    const uint32_t kBase = sptr(sK), vBase = sptr(sV);

    const int sr  = tid >> 4;        // staging row 0..15
    const int seg = tid & 15;

    const int ntiles = 8 * qt + 8;

    auto prefetchKV = [&](int tile) {
        const int slot = tile % 3;
        const float* kp = Kn + (((size_t)(b * SEQ + tile * BK + sr)) * NUM_HEADS + h) * QK_DIM + seg * 16;
        uint32_t kd = kBase + ((slot * BK * SKS + sr * SKS + seg * 16) << 2);
        CP16(kd, kp); CP16(kd + 16, kp + 4); CP16(kd + 32, kp + 8); CP16(kd + 48, kp + 12);
        const float* vp = Vp + ((size_t)(b * SEQ + tile * BK + sr)) * D_MODEL + h * HEAD_DIM + seg * 8;
        uint32_t vd = vBase + ((slot * BK * SVS + sr * SVS + seg * 8) << 2);
        CP16(vd, vp); CP16(vd + 16, vp + 4);
    };

    prefetchKV(0); CP_COMMIT();
    prefetchKV(1); CP_COMMIT();

    // stage Q (natural order, pre-rounded; scale = 2^-4 exact)
    {
        const int r = tid >> 1, d0 = (tid & 1) * 128;
        const float* qp = Qn + (((size_t)(b * SEQ + qt * BQ + r)) * NUM_HEADS + h) * QK_DIM + d0;
        uint32_t* dst = sQ + r * SQS + d0;
        const float sc = 0.0625f;
#pragma unroll
        for (int j = 0; j < 32; j++) {
            float4 v = *(const float4*)(qp + j * 4);
            *(uint4*)(dst + j * 4) = make_uint4(
                __float_as_uint(v.x * sc), __float_as_uint(v.y * sc),
                __float_as_uint(v.z * sc), __float_as_uint(v.w * sc));
        }
    }

    float oacc[16][4];
#pragma unroll
    for (int dt = 0; dt < 16; dt++)
#pragma unroll
        for (int e = 0; e < 4; e++) oacc[dt][e] = 0.f;
    float mA = -3e38f, mB = -3e38f, lA = 0.f, lB = 0.f;

    for (int tt = 0; tt < ntiles; tt++) {
        CP_WAIT1();
        __syncthreads();
        if (tt + 2 < ntiles) prefetchKV(tt + 2);
        CP_COMMIT();

        const uint32_t* sKb = sK + (tt % 3) * BK * SKS;
        const uint32_t* sVb = sV + (tt % 3) * BK * SVS;

        // S = Q @ K^T  (K packed: one LDS.128 = 4 b-operands per key-row)
        float sacc[2][4];
#pragma unroll
        for (int j = 0; j < 2; j++)
#pragma unroll
            for (int e = 0; e < 4; e++) sacc[j][e] = 0.f;

#pragma unroll
        for (int c = 0; c < 16; c++) {
            uint32_t a0[4], a1[4];
            ldmx4(a0, qAddr + c * 64);
            ldmx4(a1, qAddr + c * 64 + 32);
#pragma unroll
            for (int j = 0; j < 2; j++) {
                const uint4 kf = *(const uint4*)&sKb[(j * 8 + g) * SKS + c * 16 + t * 4];
                mma8(sacc[j], a0[0], a0[1], a0[2], a0[3], kf.x, kf.y);
                mma8(sacc[j], a1[0], a1[1], a1[2], a1[3], kf.z, kf.w);
            }
        }

        if (tt >= 8 * qt) {   // diagonal-region masking
            const int kb = tt * BK + 2 * t;
            const int qA = qt * BQ + q0 + g, qB = qA + 8;
#pragma unroll
            for (int j = 0; j < 2; j++) {
                int k0g = kb + j * 8;
                if (k0g     > qA) sacc[j][0] = -3e38f;
                if (k0g + 1 > qA) sacc[j][1] = -3e38f;
                if (k0g     > qB) sacc[j][2] = -3e38f;
                if (k0g + 1 > qB) sacc[j][3] = -3e38f;
            }
        }

        // online softmax (rows owned by quads)
        float rmA = fmaxf(fmaxf(sacc[0][0], sacc[0][1]), fmaxf(sacc[1][0], sacc[1][1]));
        float rmB = fmaxf(fmaxf(sacc[0][2], sacc[0][3]), fmaxf(sacc[1][2], sacc[1][3]));
        rmA = fmaxf(rmA, __shfl_xor_sync(0xffffffffu, rmA, 1));
        rmA = fmaxf(rmA, __shfl_xor_sync(0xffffffffu, rmA, 2));
        rmB = fmaxf(rmB, __shfl_xor_sync(0xffffffffu, rmB, 1));
        rmB = fmaxf(rmB, __shfl_xor_sync(0xffffffffu, rmB, 2));
        float mnA = fmaxf(mA, rmA), mnB = fmaxf(mB, rmB);
        float aAl = fast_exp(mA - mnA), aBl = fast_exp(mB - mnB);
        mA = mnA; mB = mnB;

        float lsA = 0.f, lsB = 0.f;
        uint32_t* pA = sP + (q0 + g) * SPS;
        uint32_t* pB = pA + 8 * SPS;
#pragma unroll
        for (int j = 0; j < 2; j++) {
            uint32_t p0 = f2tf(fast_exp(sacc[j][0] - mnA));
            uint32_t p1 = f2tf(fast_exp(sacc[j][1] - mnA));
            uint32_t p2 = f2tf(fast_exp(sacc[j][2] - mnB));
            uint32_t p3 = f2tf(fast_exp(sacc[j][3] - mnB));
            lsA += __uint_as_float(p0) + __uint_as_float(p1);
            lsB += __uint_as_float(p2) + __uint_as_float(p3);
            pA[j * 8 + 2 * t] = p0; pA[j * 8 + 2 * t + 1] = p1;
            pB[j * 8 + 2 * t] = p2; pB[j * 8 + 2 * t + 1] = p3;
        }
        lsA += __shfl_xor_sync(0xffffffffu, lsA, 1);
        lsA += __shfl_xor_sync(0xffffffffu, lsA, 2);
        lsB += __shfl_xor_sync(0xffffffffu, lsB, 1);
        lsB += __shfl_xor_sync(0xffffffffu, lsB, 2);
        lA = lA * aAl + lsA;
        lB = lB * aBl + lsB;

#pragma unroll
        for (int dt = 0; dt < 16; dt++) {
            oacc[dt][0] *= aAl; oacc[dt][1] *= aAl;
            oacc[dt][2] *= aBl; oacc[dt][3] *= aBl;
        }
        __syncwarp();

        // O += P @ V  (V packed: one LDS.128 = 4 consecutive dt operands)
#pragma unroll
        for (int k0 = 0; k0 < BK; k0 += 8) {
            uint32_t p[4];
            ldmx4(p, pAddr + k0 * 4);
            const uint32_t* vr0 = sVb + (k0 + t) * SVS + g * 16;
            const uint32_t* vr1 = sVb + (k0 + t + 4) * SVS + g * 16;
#pragma unroll
            for (int u = 0; u < 4; u++) {
                const uint4 v0 = *(const uint4*)&vr0[u * 4];
                const uint4 v1 = *(const uint4*)&vr1[u * 4];
                mma8(oacc[u * 4 + 0], p[0], p[1], p[2], p[3], v0.x, v1.x);
                mma8(oacc[u * 4 + 1], p[0], p[1], p[2], p[3], v0.y, v1.y);
                mma8(oacc[u * 4 + 2], p[0], p[1], p[2], p[3], v0.z, v1.z);
                mma8(oacc[u * 4 + 3], p[0], p[1], p[2], p[3], v0.w, v1.w);
            }
        }
    }

    // normalize + write (rounded: feeds final tf32 GEMM)
    float iA = 1.f / lA, iB = 1.f / lB;
    float* oA = Op + ((size_t)(b * SEQ + qt * BQ + q0 + g)) * D_MODEL + h * HEAD_DIM;
    float* oB = oA + (size_t)8 * D_MODEL;
#pragma unroll
    for (int dt = 0; dt < 16; dt++) {
        int c = dt * 8 + 2 * t;
        *(uint2*)(oA + c) = make_uint2(f2tf(oacc[dt][0] * iA), f2tf(oacc[dt][1] * iA));
        *(uint2*)(oB + c) = make_uint2(f2tf(oacc[dt][2] * iB), f2tf(oacc[dt][3] * iB));
    }
}

// ---------------------------------------------------------------------------
#define GEMM_SMEM (4 * 2560 * 2 * 4)   // 81920 B

extern "C" void kernel_launch(void* const* d_in, const int* in_sizes, int n_in,
                              void* d_out, int out_size)
{
    const float* inq  = (const float*)d_in[0];
    const float* ink  = (const float*)d_in[1];
    const float* Wqd  = (const float*)d_in[3];
    const float* Wkvd = (const float*)d_in[4];
    const float* Wqu  = (const float*)d_in[5];
    const float* Wku  = (const float*)d_in[6];
    const float* Wvu  = (const float*)d_in[7];
    const float* Wqr  = (const float*)d_in[8];
    const float* Wkr  = (const float*)d_in[9];
    const float* Wo   = (const float*)d_in[10];
    const float* bo   = (const float*)d_in[11];
    float* out = (float*)d_out;

    float *qlat, *kvlat, *qnew, *knew, *vbuf, *attn, *qrt, *krt;
    float *rinq, *rink, *tWqd, *tWkvd, *tWqu, *tWqr, *tWku, *tWvu, *tWkr, *tWo;
    cudaGetSymbolAddress((void**)&qlat,  g_qlat);
    cudaGetSymbolAddress((void**)&kvlat, g_kvlat);
    cudaGetSymbolAddress((void**)&qnew,  g_qnew);
    cudaGetSymbolAddress((void**)&knew,  g_knew);
    cudaGetSymbolAddress((void**)&vbuf,  g_v);
    cudaGetSymbolAddress((void**)&attn,  g_attn);
    cudaGetSymbolAddress((void**)&qrt,   g_qrt);
    cudaGetSymbolAddress((void**)&krt,   g_krt);
    cudaGetSymbolAddress((void**)&rinq,  g_rinq);
    cudaGetSymbolAddress((void**)&rink,  g_rink);
    cudaGetSymbolAddress((void**)&tWqd,  g_tWqd);
    cudaGetSymbolAddress((void**)&tWkvd, g_tWkvd);
    cudaGetSymbolAddress((void**)&tWqu,  g_tWqu);
    cudaGetSymbolAddress((void**)&tWqr,  g_tWqr);
    cudaGetSymbolAddress((void**)&tWku,  g_tWku);
    cudaGetSymbolAddress((void**)&tWvu,  g_tWvu);
    cudaGetSymbolAddress((void**)&tWkr,  g_tWkr);
    cudaGetSymbolAddress((void**)&tWo,   g_tWo);

    cudaFuncSetAttribute(tf32gemm,
                         cudaFuncAttributeMaxDynamicSharedMemorySize, GEMM_SMEM);
    cudaFuncSetAttribute(mla_attn_tf32,
                         cudaFuncAttributeMaxDynamicSharedMemorySize, ATT_SMEM_BYTES);

    // ---- pre-pass: round inputs, transpose+pack weights ----
    const int NQ = ROWS * D_MODEL;
    roundcopy<<<NQ / 1024, 256>>>(inq, rinq, NQ);
    roundcopy<<<NQ / 1024, 256>>>(ink, rink, NQ);
    dim3 tb(32, 8);
    wtrans<<<dim3(Q_LATD / 32,  D_MODEL / 32), tb>>>(Wqd,  tWqd,  D_MODEL, Q_LATD);
    wtrans<<<dim3(KV_LATD / 32, D_MODEL / 32), tb>>>(Wkvd, tWkvd, D_MODEL, KV_LATD);
    wtrans<<<dim3(D_MODEL / 32, Q_LATD / 32),  tb>>>(Wqu,  tWqu,  Q_LATD,  D_MODEL);
    wtrans<<<dim3(D_MODEL / 32, Q_LATD / 32),  tb>>>(Wqr,  tWqr,  Q_LATD,  D_MODEL);
    wtrans<<<dim3(D_MODEL / 32, KV_LATD / 32), tb>>>(Wku,  tWku,  KV_LATD, D_MODEL);
    wtrans<<<dim3(D_MODEL / 32, KV_LATD / 32), tb>>>(Wvu,  tWvu,  KV_LATD, D_MODEL);
    wtrans<<<dim3(HEAD_DIM / 32, D_MODEL / 32), tb>>>(Wkr, tWkr,  D_MODEL, HEAD_DIM);
    wtrans<<<dim3(D_MODEL / 32, D_MODEL / 32), tb>>>(Wo,   tWo,   D_MODEL, D_MODEL);

    // 1) q_latent
    tf32gemm<<<dim3(Q_LATD / 128, ROWS / 128), 256, GEMM_SMEM>>>(
        rinq, tWqd, qlat, nullptr, ROWS, Q_LATD, D_MODEL, Q_LATD, 0, 1);
    // 2) kv_latent
    tf32gemm<<<dim3(KV_LATD / 128, ROWS / 128), 256, GEMM_SMEM>>>(
        rink, tWkvd, kvlat, nullptr, ROWS, KV_LATD, D_MODEL, KV_LATD, 0, 1);
    // 3) q_proj -> q_new[..., 0:128] (interleave)
    tf32gemm<<<dim3(D_MODEL / 128, ROWS / 128), 256, GEMM_SMEM>>>(
        qlat, tWqu, qnew, nullptr, ROWS, D_MODEL, Q_LATD, 4096, 1, 1);
    // 4) q_rope pre-projection
    tf32gemm<<<dim3(D_MODEL / 128, ROWS / 128), 256, GEMM_SMEM>>>(
        qlat, tWqr, qrt, nullptr, ROWS, D_MODEL, Q_LATD, D_MODEL, 0, 1);
    // 5) rope(q) -> q_new[..., 128:256]
    rope_q_kernel<<<dim3(4, ROWS), 256>>>(qrt, qnew);
    // 6) k_proj -> k_new[..., 0:128] (interleave + kpack)
    tf32gemm<<<dim3(D_MODEL / 128, ROWS / 128), 256, GEMM_SMEM>>>(
        kvlat, tWku, knew, nullptr, ROWS, D_MODEL, KV_LATD, 4096, 2, 1);
    // 7) v_proj (vpack)
    tf32gemm<<<dim3(D_MODEL / 128, ROWS / 128), 256, GEMM_SMEM>>>(
        kvlat, tWvu, vbuf, nullptr, ROWS, D_MODEL, KV_LATD, D_MODEL, 3, 1);
    // 8) k_rope pre-projection
    tf32gemm<<<dim3(HEAD_DIM / 128, ROWS / 128), 256, GEMM_SMEM>>>(
        rink, tWkr, krt, nullptr, ROWS, HEAD_DIM, D_MODEL, HEAD_DIM, 0, 1);
    // 9) rope(k) + broadcast (kpack) -> k_new[..., 128:256]
    rope_k_kernel<<<ROWS, 64>>>(krt, knew);

    // 10) causal flash attention
    mla_attn_tf32<<<dim3(SEQ / BQ, NUM_HEADS, BATCH), 256, ATT_SMEM_BYTES>>>(
        qnew, knew, vbuf, attn);

    // 11) final projection + bias
    tf32gemm<<<dim3(D_MODEL / 128, ROWS / 128), 256, GEMM_SMEM>>>(
        attn, tWo, out, bo, ROWS, D_MODEL, D_MODEL, D_MODEL, 0, 0);
}

// round 6
// speedup vs baseline: 1.0731x; 1.0731x over previous
#include <cuda_runtime.h>
#include <math.h>
#include <stdint.h>

#define D_MODEL   2048
#define Q_LATD    1536
#define KV_LATD   512
#define NUM_HEADS 16
#define HEAD_DIM  128
#define BATCH     2
#define SEQ       2048
#define ROWS      (BATCH * SEQ)      // 4096
#define QK_DIM    256                // head_dim(128) + rope(128)

// ---------------- scratch (device globals; no allocation allowed) ----------
__device__ float g_qlat[ROWS * Q_LATD];
__device__ float g_kvlat[ROWS * KV_LATD];
__device__ float g_qnew[(size_t)ROWS * NUM_HEADS * QK_DIM];   // [b,s,h,256] natural
__device__ float g_knew[(size_t)ROWS * NUM_HEADS * QK_DIM];   // [b,s,h,256] k-packed
__device__ float g_v[(size_t)ROWS * D_MODEL];                 // [b,s,h*128] v-packed
__device__ float g_attn[(size_t)ROWS * D_MODEL];
__device__ float g_qrt[(size_t)ROWS * D_MODEL];
__device__ float g_krt[(size_t)ROWS * HEAD_DIM];

// ---------------- helpers --------------------------------------------------
__device__ __forceinline__ uint32_t f2tf(float x) {
    uint32_t u;
    asm("cvt.rna.tf32.f32 %0, %1;" : "=r"(u) : "f"(x));
    return u;
}

__device__ __forceinline__ uint32_t sptr(const void* p) {
    return (uint32_t)__cvta_generic_to_shared(p);
}

__device__ __forceinline__ void mma8(float c[4],
    uint32_t a0, uint32_t a1, uint32_t a2, uint32_t a3,
    uint32_t b0, uint32_t b1)
{
    asm volatile(
        "mma.sync.aligned.m16n8k8.row.col.f32.tf32.tf32.f32 "
        "{%0,%1,%2,%3}, {%4,%5,%6,%7}, {%8,%9}, {%0,%1,%2,%3};\n"
        : "+f"(c[0]), "+f"(c[1]), "+f"(c[2]), "+f"(c[3])
        : "r"(a0), "r"(a1), "r"(a2), "r"(a3), "r"(b0), "r"(b1));
}

__device__ __forceinline__ void ldmx4(uint32_t a[4], uint32_t addr) {
    asm volatile(
        "ldmatrix.sync.aligned.m8n8.x4.shared.b16 {%0,%1,%2,%3}, [%4];"
        : "=r"(a[0]), "=r"(a[1]), "=r"(a[2]), "=r"(a[3]) : "r"(addr));
}

#define CP16(dst, src) \
    asm volatile("cp.async.cg.shared.global [%0], [%1], 16;" :: "r"(dst), "l"(src))
#define CP_COMMIT() asm volatile("cp.async.commit_group;" ::: "memory")
#define CP_WAIT1()  asm volatile("cp.async.wait_group 1;" ::: "memory")

// exp(x) for x <= 0 on the FMA pipe only (no MUFU)
__device__ __forceinline__ float fast_exp(float x) {
    float y  = fmaxf(x * 1.4426950408889634f, -126.0f);
    float tb = y + 12582912.0f;
    float nf = tb - 12582912.0f;
    float u  = (y - nf) * 0.6931471805599453f;
    float p  = fmaf(u, 0.008333334f, 0.041666668f);
    p = fmaf(p, u, 0.16666667f);
    p = fmaf(p, u, 0.5f);
    p = fmaf(p, u, 1.0f);
    p = fmaf(p, u, 1.0f);
    return p * __int_as_float(((int)nf + 127) << 23);
}

// digit-swap within a 16-chunk: stored pos 4t+j holds original t+4j
__device__ __forceinline__ int permk(int k) {
    return (k & ~15) | (((k & 3) << 2) | ((k >> 2) & 3));
}

// ---------------- tf32 GEMM: C[M,N] = A[M,K] @ B[K,N] ----------------------
// block 128x128, BK=16, 256 thr / 8 warps, warp tile 64x32, double-buffered.
// A frags via ldmatrix (plain [m][20] layout). B frags scalar ([k][136]).
// Epilogue mode: 0 identity; 1 head-interleave; 2 interleave+kpack; 3 vpack.
__global__ void __launch_bounds__(256, 2) tf32gemm(
    const float* __restrict__ A, const float* __restrict__ B,
    float* __restrict__ C, const float* __restrict__ bias,
    int M, int N, int K, int ldc, int mode, int rnd)
{
    __shared__ uint32_t As[2][128 * 20];   // [m][k] rows of 16 + pad4
    __shared__ uint32_t Bs[2][16 * 136];   // [k][n]

    const int tid  = threadIdx.x;
    const int lane = tid & 31, w = tid >> 5;
    const int g = lane >> 2, t = lane & 3;
    const int wm = (w & 1) * 64, wn = (w >> 1) * 32;
    const int bm = blockIdx.y * 128, bn = blockIdx.x * 128;

    const int am = tid >> 1, ak = (tid & 1) * 8;
    const int bk = tid >> 4, bn0 = (tid & 15) * 8;
    const float* Ag = A + (size_t)(bm + am) * K + ak;
    const float* Bg = B + (size_t)bk * N + bn + bn0;

    const uint32_t aAddr = sptr(&As[0][0]) +
        (((wm + (lane & 15)) * 20 + ((lane >> 4) << 2)) << 2);

    float acc[4][4][4];
#pragma unroll
    for (int i = 0; i < 4; i++)
#pragma unroll
        for (int j = 0; j < 4; j++)
#pragma unroll
            for (int e = 0; e < 4; e++) acc[i][j][e] = 0.f;

    const int nk = K >> 4;

    float4 ra0 = *(const float4*)Ag;
    float4 ra1 = *(const float4*)(Ag + 4);
    float4 rb0 = *(const float4*)Bg;
    float4 rb1 = *(const float4*)(Bg + 4);

    *(uint4*)&As[0][am * 20 + ak] =
        make_uint4(f2tf(ra0.x), f2tf(ra0.y), f2tf(ra0.z), f2tf(ra0.w));
    *(uint4*)&As[0][am * 20 + ak + 4] =
        make_uint4(f2tf(ra1.x), f2tf(ra1.y), f2tf(ra1.z), f2tf(ra1.w));
    *(uint4*)&Bs[0][bk * 136 + bn0] =
        make_uint4(f2tf(rb0.x), f2tf(rb0.y), f2tf(rb0.z), f2tf(rb0.w));
    *(uint4*)&Bs[0][bk * 136 + bn0 + 4] =
        make_uint4(f2tf(rb1.x), f2tf(rb1.y), f2tf(rb1.z), f2tf(rb1.w));

    if (nk > 1) {
        ra0 = *(const float4*)(Ag + 16);
        ra1 = *(const float4*)(Ag + 20);
        rb0 = *(const float4*)(Bg + (size_t)16 * N);
        rb1 = *(const float4*)(Bg + (size_t)16 * N + 4);
    }
    __syncthreads();

    for (int kt = 0; kt < nk; kt++) {
        const int cur = kt & 1;
        const uint32_t aS = aAddr + cur * 10240;
#pragma unroll
        for (int ks = 0; ks < 2; ks++) {
            const int k0 = ks * 8;
            uint32_t af[4][4], bf[4][2];
#pragma unroll
            for (int mt = 0; mt < 4; mt++)
                ldmx4(af[mt], aS + mt * 1280 + ks * 32);
#pragma unroll
            for (int nt = 0; nt < 4; nt++) {
                const int n = wn + nt * 8 + g;
                bf[nt][0] = Bs[cur][(k0 + t) * 136 + n];
                bf[nt][1] = Bs[cur][(k0 + t + 4) * 136 + n];
            }
#pragma unroll
            for (int mt = 0; mt < 4; mt++)
#pragma unroll
                for (int nt = 0; nt < 4; nt++)
                    mma8(acc[mt][nt], af[mt][0], af[mt][1], af[mt][2], af[mt][3],
                         bf[nt][0], bf[nt][1]);
        }
        if (kt + 1 < nk) {
            const int nxt = cur ^ 1;
            *(uint4*)&As[nxt][am * 20 + ak] =
                make_uint4(f2tf(ra0.x), f2tf(ra0.y), f2tf(ra0.z), f2tf(ra0.w));
            *(uint4*)&As[nxt][am * 20 + ak + 4] =
                make_uint4(f2tf(ra1.x), f2tf(ra1.y), f2tf(ra1.z), f2tf(ra1.w));
            *(uint4*)&Bs[nxt][bk * 136 + bn0] =
                make_uint4(f2tf(rb0.x), f2tf(rb0.y), f2tf(rb0.z), f2tf(rb0.w));
            *(uint4*)&Bs[nxt][bk * 136 + bn0 + 4] =
                make_uint4(f2tf(rb1.x), f2tf(rb1.y), f2tf(rb1.z), f2tf(rb1.w));
            if (kt + 2 < nk) {
                const float* Ap = Ag + (kt + 2) * 16;
                ra0 = *(const float4*)Ap;
                ra1 = *(const float4*)(Ap + 4);
                const float* Bp = Bg + (size_t)(kt + 2) * 16 * N;
                rb0 = *(const float4*)Bp;
                rb1 = *(const float4*)(Bp + 4);
            }
        }
        __syncthreads();
    }

#pragma unroll
    for (int mt = 0; mt < 4; mt++) {
#pragma unroll
        for (int nt = 0; nt < 4; nt++) {
            const int r = bm + wm + mt * 16 + g;
            const int c = bn + wn + nt * 8 + 2 * t;
#pragma unroll
            for (int e = 0; e < 4; e++) {
                const int rr = r + ((e >> 1) << 3);
                const int cc = c + (e & 1);
                float v = acc[mt][nt][e];
                if (bias) v += bias[cc];
                if (rnd) v = __uint_as_float(f2tf(v));
                int oc;
                if (mode == 0)      oc = cc;
                else if (mode == 1) oc = ((cc >> 7) << 8) + (cc & 127);
                else if (mode == 2) oc = ((cc >> 7) << 8) + permk(cc & 127);
                else {
                    int ww = cc & 127;
                    oc = (cc & ~127) + ((ww & 7) << 4) + (ww >> 3);
                }
                C[(size_t)rr * ldc + oc] = v;
            }
        }
    }
}

// ---------------- rope on q (full 2048 dims) -> q_new[...,128:256] ---------
__global__ void rope_q_kernel(const float* __restrict__ in, float* __restrict__ qnew)
{
    int j = blockIdx.x * blockDim.x + threadIdx.x;
    int row = blockIdx.y;
    if (j >= 1024) return;
    int pos = row & (SEQ - 1);
    float inv = powf(10000.0f, -(float)j * (1.0f / 1024.0f));
    float ang = (float)pos * inv;
    float sn, cs;
    sincosf(ang, &sn, &cs);
    float x1 = in[(size_t)row * 2048 + j];
    float x2 = in[(size_t)row * 2048 + j + 1024];
    float o1 = __uint_as_float(f2tf(x1 * cs - x2 * sn));
    float o2 = __uint_as_float(f2tf(x2 * cs + x1 * sn));
    int c1 = j, c2 = j + 1024;
    qnew[(size_t)row * 4096 + (c1 >> 7) * 256 + (c1 & 127) + 128] = o1;
    qnew[(size_t)row * 4096 + (c2 >> 7) * 256 + (c2 & 127) + 128] = o2;
}

// ---------------- rope on k + broadcast to all heads (k-packed) ------------
__global__ void rope_k_kernel(const float* __restrict__ in, float* __restrict__ knew)
{
    int j = threadIdx.x;          // 0..63
    int row = blockIdx.x;
    int pos = row & (SEQ - 1);
    float inv = powf(10000.0f, -(float)j * (1.0f / 64.0f));
    float ang = (float)pos * inv;
    float sn, cs;
    sincosf(ang, &sn, &cs);
    float x1 = in[(size_t)row * 128 + j];
    float x2 = in[(size_t)row * 128 + j + 64];
    float o1 = __uint_as_float(f2tf(x1 * cs - x2 * sn));
    float o2 = __uint_as_float(f2tf(x2 * cs + x1 * sn));
    const int p1 = permk(128 + j);
    const int p2 = permk(128 + j + 64);
    float* base = knew + (size_t)row * 4096;
#pragma unroll
    for (int h = 0; h < NUM_HEADS; h++) {
        base[h * 256 + p1] = o1;
        base[h * 256 + p2] = o2;
    }
}

// ---------------- flash attention v4.1 -------------------------------------
// Bq=128 (8 warps x 16 rows), Bk=16, 3-buffer cp.async K/V, packed K/V frags.
#define BQ  128
#define BK  16
#define SQS 260   // % 32 == 4 -> conflict-free ldmatrix rows
#define SKS 272   // % 32 == 16 -> conflict-free LDS.128 K frags
#define SVS 132   // % 32 == 4  -> conflict-free LDS.128 V frags
#define SPS 36
#define Q_WORDS  (BQ * SQS)              // 33280
#define K_WORDS  (3 * BK * SKS)          // 13056
#define V_WORDS  (3 * BK * SVS)          // 6336
#define P_WORDS  (BQ * SPS)              // 4608
#define ATT_SMEM_BYTES ((Q_WORDS + K_WORDS + V_WORDS + P_WORDS) * 4)  // 229120

__global__ void __launch_bounds__(256, 1) mla_attn_tf32(
    const float* __restrict__ Qn, const float* __restrict__ Kn,
    const float* __restrict__ Vp, float* __restrict__ Op)
{
    extern __shared__ uint32_t sw[];
    uint32_t* sQ = sw;
    uint32_t* sK = sQ + Q_WORDS;
    uint32_t* sV = sK + K_WORDS;
    uint32_t* sP = sV + V_WORDS;

    const int tid = threadIdx.x, lane = tid & 31, w = tid >> 5;
    const int g = lane >> 2, t = lane & 3;
    const int qt = blockIdx.x, h = blockIdx.y, b = blockIdx.z;
    const int q0 = w * 16;

    const uint32_t qAddr = sptr(sQ) +
        (((q0 + (lane & 15)) * SQS + ((lane >> 4) << 2)) << 2);
    const uint32_t pAddr = sptr(sP) +
        (((q0 + (lane & 15)) * SPS + ((lane >> 4) << 2)) << 2);
    const uint32_t kBase = sptr(sK), vBase = sptr(sV);

    const int sr  = tid >> 4;        // staging row 0..15
    const int seg = tid & 15;

    const int ntiles = 8 * qt + 8;

    auto prefetchKV = [&](int tile) {
        const int slot = tile % 3;
        const float* kp = Kn + (((size_t)(b * SEQ + tile * BK + sr)) * NUM_HEADS + h) * QK_DIM + seg * 16;
        uint32_t kd = kBase + ((slot * BK * SKS + sr * SKS + seg * 16) << 2);
        CP16(kd, kp); CP16(kd + 16, kp + 4); CP16(kd + 32, kp + 8); CP16(kd + 48, kp + 12);
        const float* vp = Vp + ((size_t)(b * SEQ + tile * BK + sr)) * D_MODEL + h * HEAD_DIM + seg * 8;
        uint32_t vd = vBase + ((slot * BK * SVS + sr * SVS + seg * 8) << 2);
        CP16(vd, vp); CP16(vd + 16, vp + 4);
    };

    prefetchKV(0); CP_COMMIT();
    prefetchKV(1); CP_COMMIT();

    // stage Q (natural order, pre-rounded; scale = 2^-4 exact)
    {
        const int r = tid >> 1, d0 = (tid & 1) * 128;
        const float* qp = Qn + (((size_t)(b * SEQ + qt * BQ + r)) * NUM_HEADS + h) * QK_DIM + d0;
        uint32_t* dst = sQ + r * SQS + d0;
        const float sc = 0.0625f;
#pragma unroll
        for (int j = 0; j < 32; j++) {
            float4 v = *(const float4*)(qp + j * 4);
            *(uint4*)(dst + j * 4) = make_uint4(
                __float_as_uint(v.x * sc), __float_as_uint(v.y * sc),
                __float_as_uint(v.z * sc), __float_as_uint(v.w * sc));
        }
    }

    float oacc[16][4];
#pragma unroll
    for (int dt = 0; dt < 16; dt++)
#pragma unroll
        for (int e = 0; e < 4; e++) oacc[dt][e] = 0.f;
    float mA = -3e38f, mB = -3e38f, lA = 0.f, lB = 0.f;

    for (int tt = 0; tt < ntiles; tt++) {
        CP_WAIT1();
        __syncthreads();
        if (tt + 2 < ntiles) prefetchKV(tt + 2);
        CP_COMMIT();

        const uint32_t* sKb = sK + (tt % 3) * BK * SKS;
        const uint32_t* sVb = sV + (tt % 3) * BK * SVS;

        // S = Q @ K^T  (K packed: one LDS.128 = 4 b-operands per key-row)
        float sacc[2][4];
#pragma unroll
        for (int j = 0; j < 2; j++)
#pragma unroll
            for (int e = 0; e < 4; e++) sacc[j][e] = 0.f;

#pragma unroll
        for (int c = 0; c < 16; c++) {
            uint32_t a0[4], a1[4];
            ldmx4(a0, qAddr + c * 64);
            ldmx4(a1, qAddr + c * 64 + 32);
#pragma unroll
            for (int j = 0; j < 2; j++) {
                const uint4 kf = *(const uint4*)&sKb[(j * 8 + g) * SKS + c * 16 + t * 4];
                mma8(sacc[j], a0[0], a0[1], a0[2], a0[3], kf.x, kf.y);
                mma8(sacc[j], a1[0], a1[1], a1[2], a1[3], kf.z, kf.w);
            }
        }

        if (tt >= 8 * qt) {   // diagonal-region masking
            const int kb = tt * BK + 2 * t;
            const int qA = qt * BQ + q0 + g, qB = qA + 8;
#pragma unroll
            for (int j = 0; j < 2; j++) {
                int k0g = kb + j * 8;
                if (k0g     > qA) sacc[j][0] = -3e38f;
                if (k0g + 1 > qA) sacc[j][1] = -3e38f;
                if (k0g     > qB) sacc[j][2] = -3e38f;
                if (k0g + 1 > qB) sacc[j][3] = -3e38f;
            }
        }

        // online softmax (rows owned by quads)
        float rmA = fmaxf(fmaxf(sacc[0][0], sacc[0][1]), fmaxf(sacc[1][0], sacc[1][1]));
        float rmB = fmaxf(fmaxf(sacc[0][2], sacc[0][3]), fmaxf(sacc[1][2], sacc[1][3]));
        rmA = fmaxf(rmA, __shfl_xor_sync(0xffffffffu, rmA, 1));
        rmA = fmaxf(rmA, __shfl_xor_sync(0xffffffffu, rmA, 2));
        rmB = fmaxf(rmB, __shfl_xor_sync(0xffffffffu, rmB, 1));
        rmB = fmaxf(rmB, __shfl_xor_sync(0xffffffffu, rmB, 2));
        float mnA = fmaxf(mA, rmA), mnB = fmaxf(mB, rmB);
        float aAl = fast_exp(mA - mnA), aBl = fast_exp(mB - mnB);
        mA = mnA; mB = mnB;

        float lsA = 0.f, lsB = 0.f;
        uint32_t* pA = sP + (q0 + g) * SPS;
        uint32_t* pB = pA + 8 * SPS;
#pragma unroll
        for (int j = 0; j < 2; j++) {
            uint32_t p0 = f2tf(fast_exp(sacc[j][0] - mnA));
            uint32_t p1 = f2tf(fast_exp(sacc[j][1] - mnA));
            uint32_t p2 = f2tf(fast_exp(sacc[j][2] - mnB));
            uint32_t p3 = f2tf(fast_exp(sacc[j][3] - mnB));
            lsA += __uint_as_float(p0) + __uint_as_float(p1);
            lsB += __uint_as_float(p2) + __uint_as_float(p3);
            pA[j * 8 + 2 * t] = p0; pA[j * 8 + 2 * t + 1] = p1;
            pB[j * 8 + 2 * t] = p2; pB[j * 8 + 2 * t + 1] = p3;
        }
        lsA += __shfl_xor_sync(0xffffffffu, lsA, 1);
        lsA += __shfl_xor_sync(0xffffffffu, lsA, 2);
        lsB += __shfl_xor_sync(0xffffffffu, lsB, 1);
        lsB += __shfl_xor_sync(0xffffffffu, lsB, 2);
        lA = lA * aAl + lsA;
        lB = lB * aBl + lsB;

#pragma unroll
        for (int dt = 0; dt < 16; dt++) {
            oacc[dt][0] *= aAl; oacc[dt][1] *= aAl;
            oacc[dt][2] *= aBl; oacc[dt][3] *= aBl;
        }
        __syncwarp();

        // O += P @ V  (V packed: one LDS.128 = 4 consecutive dt operands)
#pragma unroll
        for (int k0 = 0; k0 < BK; k0 += 8) {
            uint32_t p[4];
            ldmx4(p, pAddr + k0 * 4);
            const uint32_t* vr0 = sVb + (k0 + t) * SVS + g * 16;
            const uint32_t* vr1 = sVb + (k0 + t + 4) * SVS + g * 16;
#pragma unroll
            for (int u = 0; u < 4; u++) {
                const uint4 v0 = *(const uint4*)&vr0[u * 4];
                const uint4 v1 = *(const uint4*)&vr1[u * 4];
                mma8(oacc[u * 4 + 0], p[0], p[1], p[2], p[3], v0.x, v1.x);
                mma8(oacc[u * 4 + 1], p[0], p[1], p[2], p[3], v0.y, v1.y);
                mma8(oacc[u * 4 + 2], p[0], p[1], p[2], p[3], v0.z, v1.z);
                mma8(oacc[u * 4 + 3], p[0], p[1], p[2], p[3], v0.w, v1.w);
            }
        }
    }

    // normalize + write
    float iA = 1.f / lA, iB = 1.f / lB;
    float* oA = Op + ((size_t)(b * SEQ + qt * BQ + q0 + g)) * D_MODEL + h * HEAD_DIM;
    float* oB = oA + (size_t)8 * D_MODEL;
#pragma unroll
    for (int dt = 0; dt < 16; dt++) {
        int c = dt * 8 + 2 * t;
        *(float2*)(oA + c) = make_float2(oacc[dt][0] * iA, oacc[dt][1] * iA);
        *(float2*)(oB + c) = make_float2(oacc[dt][2] * iB, oacc[dt][3] * iB);
    }
}

// ---------------------------------------------------------------------------
extern "C" void kernel_launch(void* const* d_in, const int* in_sizes, int n_in,
                              void* d_out, int out_size)
{
    const float* inq  = (const float*)d_in[0];
    const float* ink  = (const float*)d_in[1];
    const float* Wqd  = (const float*)d_in[3];
    const float* Wkvd = (const float*)d_in[4];
    const float* Wqu  = (const float*)d_in[5];
    const float* Wku  = (const float*)d_in[6];
    const float* Wvu  = (const float*)d_in[7];
    const float* Wqr  = (const float*)d_in[8];
    const float* Wkr  = (const float*)d_in[9];
    const float* Wo   = (const float*)d_in[10];
    const float* bo   = (const float*)d_in[11];
    float* out = (float*)d_out;

    float *qlat, *kvlat, *qnew, *knew, *vbuf, *attn, *qrt, *krt;
    cudaGetSymbolAddress((void**)&qlat,  g_qlat);
    cudaGetSymbolAddress((void**)&kvlat, g_kvlat);
    cudaGetSymbolAddress((void**)&qnew,  g_qnew);
    cudaGetSymbolAddress((void**)&knew,  g_knew);
    cudaGetSymbolAddress((void**)&vbuf,  g_v);
    cudaGetSymbolAddress((void**)&attn,  g_attn);
    cudaGetSymbolAddress((void**)&qrt,   g_qrt);
    cudaGetSymbolAddress((void**)&krt,   g_krt);

    cudaFuncSetAttribute(mla_attn_tf32,
                         cudaFuncAttributeMaxDynamicSharedMemorySize, ATT_SMEM_BYTES);

    // 1) q_latent = inputs_q @ Wq_down
    tf32gemm<<<dim3(Q_LATD / 128, ROWS / 128), 256>>>(
        inq, Wqd, qlat, nullptr, ROWS, Q_LATD, D_MODEL, Q_LATD, 0, 1);
    // 2) kv_latent = inputs_k @ Wkv_down
    tf32gemm<<<dim3(KV_LATD / 128, ROWS / 128), 256>>>(
        ink, Wkvd, kvlat, nullptr, ROWS, KV_LATD, D_MODEL, KV_LATD, 0, 1);
    // 3) q_proj -> q_new[..., 0:128] (head-interleave)
    tf32gemm<<<dim3(D_MODEL / 128, ROWS / 128), 256>>>(
        qlat, Wqu, qnew, nullptr, ROWS, D_MODEL, Q_LATD, 4096, 1, 1);
    // 4) q_rope pre-projection
    tf32gemm<<<dim3(D_MODEL / 128, ROWS / 128), 256>>>(
        qlat, Wqr, qrt, nullptr, ROWS, D_MODEL, Q_LATD, D_MODEL, 0, 1);
    // 5) rope(q) -> q_new[..., 128:256]
    rope_q_kernel<<<dim3(4, ROWS), 256>>>(qrt, qnew);
    // 6) k_proj -> k_new[..., 0:128] (interleave + kpack)
    tf32gemm<<<dim3(D_MODEL / 128, ROWS / 128), 256>>>(
        kvlat, Wku, knew, nullptr, ROWS, D_MODEL, KV_LATD, 4096, 2, 1);
    // 7) v_proj (vpack)
    tf32gemm<<<dim3(D_MODEL / 128, ROWS / 128), 256>>>(
        kvlat, Wvu, vbuf, nullptr, ROWS, D_MODEL, KV_LATD, D_MODEL, 3, 1);
    // 8) k_rope pre-projection
    tf32gemm<<<dim3(HEAD_DIM / 128, ROWS / 128), 256>>>(
        ink, Wkr, krt, nullptr, ROWS, HEAD_DIM, D_MODEL, HEAD_DIM, 0, 1);
    // 9) rope(k) + broadcast (kpack) -> k_new[..., 128:256]
    rope_k_kernel<<<ROWS, 64>>>(krt, knew);

    // 10) causal flash attention (tf32, packed K/V, cp.async pipelined)
    mla_attn_tf32<<<dim3(SEQ / BQ, NUM_HEADS, BATCH), 256, ATT_SMEM_BYTES>>>(
        qnew, knew, vbuf, attn);

    // 11) final projection + bias (full precision out)
    tf32gemm<<<dim3(D_MODEL / 128, ROWS / 128), 256>>>(
        attn, Wo, out, bo, ROWS, D_MODEL, D_MODEL, D_MODEL, 0, 0);
}